// round 15
// baseline (speedup 1.0000x reference)
#include <cuda_runtime.h>
#include <cuda_bf16.h>
#include <cstdint>

// Problem constants
#define BB 2
#define TT 1024
#define CC 768
#define HH 12
#define DH 64
#define LL 4
#define HID 3072
#define VV 32000
#define BT (BB*TT)          // 2048
#define QKVN (3*CC)         // 2304

// ---------------- scratch (device globals; no cudaMalloc allowed) ----------
__device__ float g_x[BT*CC];          // residual stream
__device__ float g_h[BT*CC];          // layernorm output / rounded x copy
__device__ float g_qkv[BT*QKVN];      // fused qkv output
__device__ float g_attn[BT*CC];       // attention output (concat heads)
__device__ float g_hid[BT*HID];       // MLP hidden
__device__ float g_wqkv[LL*CC*QKVN];  // packed+rounded qkv weights [k][n]
__device__ float g_wproj[LL*CC*CC];   // rounded
__device__ float g_w1[LL*CC*HID];     // rounded
__device__ float g_w2[LL*HID*CC];     // rounded
__device__ float g_wlm[CC*VV];        // rounded
__device__ float g_rowloss[BT];       // per-row -logp[target]

__device__ __forceinline__ uint32_t f2tf32(float f) {
    uint32_t u;
    asm("cvt.rna.tf32.f32 %0, %1;" : "=r"(u) : "f"(f));
    return u;
}
__device__ __forceinline__ float tf32r(float f) {
    return __uint_as_float(f2tf32(f));
}

// ---- packed f32x2 helpers (base sm_100-family PTX, no 'a' features) -------
#define FMA2(d, a, b) asm volatile("fma.rn.f32x2 %0, %1, %2, %0;" : "+l"(d) : "l"(a), "l"(b))
#define MUL2(d, a, b) asm("mul.rn.f32x2 %0, %1, %2;" : "=l"(d) : "l"(a), "l"(b))
#define ADD2(d, a, b) asm("add.rn.f32x2 %0, %1, %2;" : "=l"(d) : "l"(a), "l"(b))
#define PACK2(d, lo, hi) asm("mov.b64 %0, {%1, %2};" : "=l"(d) : "r"(__float_as_uint(lo)), "r"(__float_as_uint(hi)))
#define UNPACK2(lo, hi, d) do { uint32_t _ul, _uh;                          \
    asm("mov.b64 {%0, %1}, %2;" : "=r"(_ul), "=r"(_uh) : "l"(d));           \
    lo = __uint_as_float(_ul); hi = __uint_as_float(_uh); } while (0)
#define LDS2B64(a, b, addr) asm volatile("ld.shared.v2.b64 {%0, %1}, [%2];" : "=l"(a), "=l"(b) : "r"(addr))

#define CP16(dst, src) asm volatile("cp.async.cg.shared.global [%0], [%1], 16;" :: "r"(dst), "l"(src))

// ---------------- weight packing: Wq/Wk/Wv [L,H,C,DH] -> [L][C][3C] (tf32) -
__global__ void pack_qkv_kernel(const float* __restrict__ Wq,
                                const float* __restrict__ Wk,
                                const float* __restrict__ Wv) {
    const long total = (long)LL * CC * QKVN;
    for (long i = (long)blockIdx.x * blockDim.x + threadIdx.x; i < total;
         i += (long)gridDim.x * blockDim.x) {
        int n = (int)(i % QKVN);
        long r = i / QKVN;
        int k = (int)(r % CC);
        int l = (int)(r / CC);
        const float* W; int nn = n;
        if (n < CC)           { W = Wq; }
        else if (n < 2*CC)    { W = Wk; nn = n - CC; }
        else                  { W = Wv; nn = n - 2*CC; }
        int h = nn >> 6, d = nn & 63;
        g_wqkv[i] = tf32r(W[(((long)l*HH + h)*CC + k)*DH + d]);
    }
}

// ---------------- dual tf32 round-copy (fewer launches) --------------------
__global__ void round_copy2_kernel(const float* __restrict__ s0, float* __restrict__ d0, long n0,
                                   const float* __restrict__ s1, float* __restrict__ d1, long n1) {
    const long stride = (long)gridDim.x * blockDim.x;
    for (long i = (long)blockIdx.x * blockDim.x + threadIdx.x; i < n0; i += stride)
        d0[i] = tf32r(s0[i]);
    for (long i = (long)blockIdx.x * blockDim.x + threadIdx.x; i < n1; i += stride)
        d1[i] = tf32r(s1[i]);
}

// ---------------- fused embed + layer-0 ln1 --------------------------------
__global__ void embed_ln_kernel(const int* __restrict__ idx,
                                const float* __restrict__ tok,
                                const float* __restrict__ pos,
                                const float* __restrict__ g,
                                const float* __restrict__ b) {
    __shared__ float rs[256], rs2[256];
    const int row = blockIdx.x;
    const int t = row % TT;
    const float* tr = tok + (long)idx[row]*CC;
    const float* pr = pos + (long)t*CC;
    float vals[CC/256];
    float s = 0.f, s2 = 0.f;
    #pragma unroll
    for (int i = 0; i < CC/256; i++) {
        int c = threadIdx.x + i*256;
        float v = tr[c] + pr[c];
        vals[i] = v;
        g_x[(long)row*CC + c] = v;
        s += v; s2 += v*v;
    }
    rs[threadIdx.x] = s; rs2[threadIdx.x] = s2;
    __syncthreads();
    for (int o = 128; o > 0; o >>= 1) {
        if (threadIdx.x < o) {
            rs[threadIdx.x]  += rs[threadIdx.x + o];
            rs2[threadIdx.x] += rs2[threadIdx.x + o];
        }
        __syncthreads();
    }
    float mean = rs[0] * (1.f/CC);
    float var  = rs2[0] * (1.f/CC) - mean*mean;
    float inv  = rsqrtf(var + 1e-5f);
    #pragma unroll
    for (int i = 0; i < CC/256; i++) {
        int c = threadIdx.x + i*256;
        g_h[(long)row*CC + c] = tf32r((vals[i] - mean) * inv * g[c] + b[c]);
    }
}

// ---------------- layernorm (rounded output) -------------------------------
__global__ void layernorm_kernel(const float* __restrict__ x,
                                 const float* __restrict__ g,
                                 const float* __restrict__ b,
                                 float* __restrict__ y) {
    __shared__ float rs[256], rs2[256];
    int row = blockIdx.x;
    const float* xr = x + (long)row*CC;
    float s = 0.f, s2 = 0.f;
    for (int c = threadIdx.x; c < CC; c += 256) {
        float v = xr[c];
        s += v; s2 += v*v;
    }
    rs[threadIdx.x] = s; rs2[threadIdx.x] = s2;
    __syncthreads();
    for (int o = 128; o > 0; o >>= 1) {
        if (threadIdx.x < o) {
            rs[threadIdx.x]  += rs[threadIdx.x + o];
            rs2[threadIdx.x] += rs2[threadIdx.x + o];
        }
        __syncthreads();
    }
    float mean = rs[0] * (1.f/CC);
    float var  = rs2[0] * (1.f/CC) - mean*mean;
    float inv  = rsqrtf(var + 1e-5f);
    for (int c = threadIdx.x; c < CC; c += 256) {
        y[(long)row*CC + c] = tf32r((xr[c] - mean) * inv * g[c] + b[c]);
    }
}

// ---------------- TF32 tensor-core GEMM, cp.async 4-stage, kc-staggered ----
#define ASTRIDE 20
#define STAGES 4

#define MMA_TF32(acc, af, bf)                                              \
    asm volatile(                                                          \
        "mma.sync.aligned.m16n8k8.row.col.f32.tf32.tf32.f32 "              \
        "{%0,%1,%2,%3},{%4,%5,%6,%7},{%8,%9},{%0,%1,%2,%3};"               \
        : "+f"((acc)[0]), "+f"((acc)[1]), "+f"((acc)[2]), "+f"((acc)[3])   \
        : "r"((af)[0]), "r"((af)[1]), "r"((af)[2]), "r"((af)[3]),          \
          "r"((bf)[0]), "r"((bf)[1]))

template<int BN, bool BIAS, bool RELU, bool RES, bool ROUND>
__global__ void __launch_bounds__(256, 2)
gemm_tf32_kernel(const float* __restrict__ A, const float* __restrict__ B,
                 const float* __restrict__ bias, const float* __restrict__ res,
                 float* __restrict__ C, int M, int N, int K) {
    constexpr int BSTRIDE = BN + 8;
    constexpr int NI = BN / 16;
    constexpr int BTPR = BN / 4;
    constexpr int BRPP = 256 / BTPR;
    constexpr int BPASS = 16 / BRPP;
    __shared__ float As[STAGES][128*ASTRIDE];
    __shared__ float Bs[STAGES][16*BSTRIDE];
    const int tid  = threadIdx.x;
    const int wid  = tid >> 5;
    const int lane = tid & 31;
    const int warpM = wid & 3;
    const int warpN = wid >> 2;
    const int gr = lane >> 2;
    const int gc = lane & 3;
    const int m0 = blockIdx.x * 128;
    const int n0 = blockIdx.y * BN;
    const int kcFirst = (wid & 1) << 3;
    const int kcSecond = kcFirst ^ 8;

    float acc[2][NI][4];
    #pragma unroll
    for (int mi = 0; mi < 2; mi++)
        #pragma unroll
        for (int ni = 0; ni < NI; ni++)
            #pragma unroll
            for (int j = 0; j < 4; j++) acc[mi][ni][j] = 0.f;

    const int aRow = tid >> 2;
    const int aCol = (tid & 3) << 2;
    const int bRow = tid / BTPR;
    const int bCol = (tid % BTPR) * 4;

    const float* Ab = A + (long)m0*K;
    const float* Bb = B + n0;
    const int nIter = K >> 4;

    #define ISSUE(it, stg) do {                                            \
        const float* Ag = Ab + ((it) << 4);                                \
        _Pragma("unroll")                                                  \
        for (int r = 0; r < 2; r++) {                                      \
            int row = aRow + r*64;                                         \
            uint32_t d_ = (uint32_t)__cvta_generic_to_shared(              \
                &As[stg][row*ASTRIDE + aCol]);                             \
            CP16(d_, Ag + (long)row*K + aCol);                             \
        }                                                                  \
        const float* Bg = Bb + (long)((it) << 4)*N;                        \
        _Pragma("unroll")                                                  \
        for (int r = 0; r < BPASS; r++) {                                  \
            int krow = bRow + r*BRPP;                                      \
            uint32_t d_ = (uint32_t)__cvta_generic_to_shared(              \
                &Bs[stg][krow*BSTRIDE + bCol]);                            \
            CP16(d_, Bg + (long)krow*N + bCol);                            \
        }                                                                  \
        asm volatile("cp.async.commit_group;");                            \
    } while (0)

    #define DO_KC(kc, stg) do {                                            \
        uint32_t af[2][4];                                                 \
        _Pragma("unroll")                                                  \
        for (int mi = 0; mi < 2; mi++) {                                   \
            int row = warpM*32 + mi*16 + gr;                               \
            af[mi][0] = __float_as_uint(As[stg][row*ASTRIDE + (kc) + gc]); \
            af[mi][1] = __float_as_uint(As[stg][(row+8)*ASTRIDE + (kc) + gc]); \
            af[mi][2] = __float_as_uint(As[stg][row*ASTRIDE + (kc) + gc + 4]); \
            af[mi][3] = __float_as_uint(As[stg][(row+8)*ASTRIDE + (kc) + gc + 4]); \
        }                                                                  \
        uint32_t bf[NI][2];                                                \
        _Pragma("unroll")                                                  \
        for (int ni = 0; ni < NI; ni++) {                                  \
            int col = warpN*(BN/2) + ni*8 + gr;                            \
            bf[ni][0] = __float_as_uint(Bs[stg][((kc)+gc)*BSTRIDE + col]); \
            bf[ni][1] = __float_as_uint(Bs[stg][((kc)+gc+4)*BSTRIDE + col]); \
        }                                                                  \
        _Pragma("unroll")                                                  \
        for (int mi = 0; mi < 2; mi++)                                     \
            _Pragma("unroll")                                              \
            for (int ni = 0; ni < NI; ni++)                                \
                MMA_TF32(acc[mi][ni], af[mi], bf[ni]);                     \
    } while (0)

    ISSUE(0, 0); ISSUE(1, 1); ISSUE(2, 2);

    for (int it = 0; it < nIter; it++) {
        const int stg = it & (STAGES-1);
        if (it + 2 < nIter)      asm volatile("cp.async.wait_group 2;");
        else if (it + 1 < nIter) asm volatile("cp.async.wait_group 1;");
        else                     asm volatile("cp.async.wait_group 0;");
        __syncthreads();

        DO_KC(kcFirst, stg);
        if (it + 3 < nIter) ISSUE(it + 3, (it + 3) & (STAGES-1));
        DO_KC(kcSecond, stg);
    }
    #undef DO_KC
    #undef ISSUE

    #pragma unroll
    for (int mi = 0; mi < 2; mi++) {
        #pragma unroll
        for (int rr = 0; rr < 2; rr++) {
            long row = m0 + warpM*32 + mi*16 + gr + rr*8;
            #pragma unroll
            for (int ni = 0; ni < NI; ni++) {
                int col = n0 + warpN*(BN/2) + ni*8 + gc*2;
                float v0 = acc[mi][ni][rr*2+0];
                float v1 = acc[mi][ni][rr*2+1];
                if (BIAS) { v0 += bias[col]; v1 += bias[col+1]; }
                if (RES)  {
                    float2 rv = *(const float2*)(res + row*N + col);
                    v0 += rv.x; v1 += rv.y;
                }
                if (RELU) { v0 = fmaxf(v0, 0.f); v1 = fmaxf(v1, 0.f); }
                if (ROUND){ v0 = tf32r(v0); v1 = tf32r(v1); }
                float2 ov; ov.x = v0; ov.y = v1;
                *(float2*)(C + row*N + col) = ov;
            }
        }
    }
}

// ------- flash attention: D-split thread pairs + 2-way split-K -------------
// 128 threads, TQ=32 queries: tid = khalf*64 + tq*2 + dhalf.
// Each thread owns 32 head dims -> ~half the registers of the R13 kernel.
// Score: partial dot over own 32 dims + one shfl_xor(1) -> full score on both
// lanes of the pair (identical, deterministic). khalf split-K merged via smem.
#define TQ 32
#define TS 16
__global__ void __launch_bounds__(128)
flash_attn_kernel(const float* __restrict__ qkv, float* __restrict__ out) {
    __shared__ float KV[2][2][TS*DH];   // [khalf][k/v][s*DH+d]   16KB
    __shared__ float mlm[2][TQ];
    __shared__ float xch[TQ*DH];        // 8KB
    const int q0 = (gridDim.x - 1 - blockIdx.x) * TQ;  // longest first
    const int bh = blockIdx.y;
    const int b  = bh / HH;
    const int h  = bh % HH;
    const int tid   = threadIdx.x;
    const int khalf = tid >> 6;
    const int sub   = tid & 63;
    const int tq    = sub >> 1;
    const int dh    = sub & 1;          // which 32-dim half
    const int t = q0 + tq;
    const float* base = qkv + (long)b*TT*QKVN;
    const int doff = dh*32;

    // q: own 32 dims packed as 16 f32x2
    uint64_t q2[16];
    {
        const float4* qr = (const float4*)(base + (long)t*QKVN + h*DH + doff);
        #pragma unroll
        for (int j = 0; j < 8; j++) {
            float4 v = qr[j];
            PACK2(q2[2*j+0], v.x, v.y);
            PACK2(q2[2*j+1], v.z, v.w);
        }
    }
    uint64_t acc2[16];
    #pragma unroll
    for (int j = 0; j < 16; j++) acc2[j] = 0ull;
    float m = -1e30f, l = 0.f;

    const int nT = (q0 + TQ) / TS;      // multiple of 2
    const int nHalf = nT >> 1;
    const int tile0 = khalf * nHalf;

    const uint32_t ksm = (uint32_t)__cvta_generic_to_shared(&KV[khalf][0][0]);
    const uint32_t vsm = (uint32_t)__cvta_generic_to_shared(&KV[khalf][1][0]);

    for (int jt = 0; jt < nHalf; jt++) {
        const int s0 = (tile0 + jt) * TS;
        __syncthreads();
        // 64 threads of this khalf load its K/V tiles (256 float4 each)
        #pragma unroll
        for (int i = 0; i < 4; i++) {
            int idx = sub + i*64;
            int s  = idx >> 4;
            int d4 = (idx & 15) << 2;
            const float* kp = base + (long)(s0+s)*QKVN + CC + h*DH + d4;
            *(float4*)&KV[khalf][0][s*DH + d4] = *(const float4*)kp;
            *(float4*)&KV[khalf][1][s*DH + d4] = *(const float4*)(kp + CC);
        }
        __syncthreads();

        float sc[TS];
        float tmax = -1e30f;
        #pragma unroll
        for (int s = 0; s < TS; s++) {
            uint32_t ka = ksm + (s*DH + doff)*4;
            uint64_t d0 = 0ull, d1 = 0ull, d2 = 0ull, d3 = 0ull;
            #pragma unroll
            for (int j = 0; j < 16; j += 4) {
                uint64_t k0, k1, k2, k3;
                LDS2B64(k0, k1, ka + j*8);
                LDS2B64(k2, k3, ka + (j+2)*8);
                FMA2(d0, q2[j+0], k0);
                FMA2(d1, q2[j+1], k1);
                FMA2(d2, q2[j+2], k2);
                FMA2(d3, q2[j+3], k3);
            }
            ADD2(d0, d0, d1); ADD2(d2, d2, d3); ADD2(d0, d0, d2);
            float lo, hi; UNPACK2(lo, hi, d0);
            float part = lo + hi;
            float full = part + __shfl_xor_sync(0xFFFFFFFFu, part, 1);
            sc[s] = (s0 + s <= t) ? full * 0.125f : -1e30f;
            tmax = fmaxf(tmax, sc[s]);
        }
        if (tmax > -1e29f) {
            float m_new = fmaxf(m, tmax);
            float alpha = __expf(m - m_new);
            l *= alpha;
            uint64_t a2; PACK2(a2, alpha, alpha);
            #pragma unroll
            for (int j = 0; j < 16; j++) MUL2(acc2[j], acc2[j], a2);
            #pragma unroll
            for (int s = 0; s < TS; s++) {
                float p = (sc[s] > -1e29f) ? __expf(sc[s] - m_new) : 0.f;
                l += p;
                uint64_t p2; PACK2(p2, p, p);
                uint32_t va = vsm + (s*DH + doff)*4;
                #pragma unroll
                for (int j = 0; j < 16; j += 2) {
                    uint64_t v0, v1;
                    LDS2B64(v0, v1, va + j*8);
                    FMA2(acc2[j+0], p2, v0);
                    FMA2(acc2[j+1], p2, v1);
                }
            }
            m = m_new;
        }
    }

    float acc[32];
    #pragma unroll
    for (int j = 0; j < 16; j++) {
        float lo, hi; UNPACK2(lo, hi, acc2[j]);
        acc[2*j] = lo; acc[2*j+1] = hi;
    }

    __syncthreads();
    if (khalf == 1) {
        if (dh == 0) { mlm[0][tq] = m; mlm[1][tq] = l; }
        #pragma unroll
        for (int j = 0; j < 32; j++)
            xch[tq*DH + doff + ((j + tq) & 31)] = acc[j];
    }
    __syncthreads();
    if (khalf == 0) {
        float m1 = mlm[0][tq], l1 = mlm[1][tq];
        float ms = fmaxf(m, m1);
        float a0 = __expf(m - ms);
        float a1 = __expf(m1 - ms);
        float inv = 1.0f / (l*a0 + l1*a1);
        float* o = out + ((long)b*TT + t)*CC + h*DH + doff;
        #pragma unroll
        for (int j = 0; j < 32; j += 4) {
            float4 v;
            v.x = tf32r((acc[j+0]*a0 + xch[tq*DH + doff + ((j+0+tq)&31)]*a1) * inv);
            v.y = tf32r((acc[j+1]*a0 + xch[tq*DH + doff + ((j+1+tq)&31)]*a1) * inv);
            v.z = tf32r((acc[j+2]*a0 + xch[tq*DH + doff + ((j+2+tq)&31)]*a1) * inv);
            v.w = tf32r((acc[j+3]*a0 + xch[tq*DH + doff + ((j+3+tq)&31)]*a1) * inv);
            *(float4*)(o + j) = v;
        }
    }
}

// ---------------- cross-entropy: single-pass online softmax (float4) -------
__global__ void loss_rows_kernel(const float* __restrict__ logits,
                                 const int* __restrict__ targets) {
    __shared__ float sm[256], ss[256];
    const int row = blockIdx.x;
    const float4* lr4 = (const float4*)(logits + (long)row*VV);
    float m = -1e30f, s = 0.f;
    for (int c4 = threadIdx.x; c4 < VV/4; c4 += 256) {
        float4 v4 = lr4[c4];
        float vm = fmaxf(fmaxf(v4.x, v4.y), fmaxf(v4.z, v4.w));
        if (vm <= m) {
            s += __expf(v4.x - m) + __expf(v4.y - m)
               + __expf(v4.z - m) + __expf(v4.w - m);
        } else {
            s = s*__expf(m - vm)
              + __expf(v4.x - vm) + __expf(v4.y - vm)
              + __expf(v4.z - vm) + __expf(v4.w - vm);
            m = vm;
        }
    }
    sm[threadIdx.x] = m; ss[threadIdx.x] = s;
    __syncthreads();
    for (int o = 128; o > 0; o >>= 1) {
        if (threadIdx.x < o) {
            float m2 = sm[threadIdx.x+o], s2 = ss[threadIdx.x+o];
            float mm = fmaxf(sm[threadIdx.x], m2);
            ss[threadIdx.x] = ss[threadIdx.x]*__expf(sm[threadIdx.x]-mm)
                            + s2*__expf(m2-mm);
            sm[threadIdx.x] = mm;
        }
        __syncthreads();
    }
    if (threadIdx.x == 0) {
        float lse = sm[0] + logf(ss[0]);
        g_rowloss[row] = lse - logits[(long)row*VV + targets[row]];
    }
}

__global__ void loss_reduce_kernel(float* __restrict__ out) {
    __shared__ float red[256];
    float s = 0.f;
    for (int i = threadIdx.x; i < BT; i += 256) s += g_rowloss[i];
    red[threadIdx.x] = s; __syncthreads();
    for (int o = 128; o > 0; o >>= 1) {
        if (threadIdx.x < o) red[threadIdx.x] += red[threadIdx.x+o];
        __syncthreads();
    }
    if (threadIdx.x == 0) *out = red[0] * (1.0f/BT);
}

// ---------------- driver ----------------------------------------------------
extern "C" void kernel_launch(void* const* d_in, const int* in_sizes, int n_in,
                              void* d_out, int out_size) {
    const int*   idx     = (const int*)  d_in[0];
    const int*   targets = (const int*)  d_in[1];
    const float* tok_emb = (const float*)d_in[2];
    const float* pos_emb = (const float*)d_in[3];
    const float* Wq      = (const float*)d_in[4];
    const float* Wk      = (const float*)d_in[5];
    const float* Wv      = (const float*)d_in[6];
    const float* Wproj   = (const float*)d_in[7];
    const float* bproj   = (const float*)d_in[8];
    const float* ln1_g   = (const float*)d_in[9];
    const float* ln1_b   = (const float*)d_in[10];
    const float* ln2_g   = (const float*)d_in[11];
    const float* ln2_b   = (const float*)d_in[12];
    const float* W1      = (const float*)d_in[13];
    const float* b1      = (const float*)d_in[14];
    const float* W2      = (const float*)d_in[15];
    const float* b2      = (const float*)d_in[16];
    const float* Wlm     = (const float*)d_in[17];
    const float* blm     = (const float*)d_in[18];
    float* out = (float*)d_out;

    float* xp;    cudaGetSymbolAddress((void**)&xp,    g_x);
    float* hp;    cudaGetSymbolAddress((void**)&hp,    g_h);
    float* qkvp;  cudaGetSymbolAddress((void**)&qkvp,  g_qkv);
    float* attnp; cudaGetSymbolAddress((void**)&attnp, g_attn);
    float* hidp;  cudaGetSymbolAddress((void**)&hidp,  g_hid);
    float* wqkvp; cudaGetSymbolAddress((void**)&wqkvp, g_wqkv);
    float* wprojp;cudaGetSymbolAddress((void**)&wprojp,g_wproj);
    float* w1p;   cudaGetSymbolAddress((void**)&w1p,   g_w1);
    float* w2p;   cudaGetSymbolAddress((void**)&w2p,   g_w2);
    float* wlmp;  cudaGetSymbolAddress((void**)&wlmp,  g_wlm);

    // Launch order: 0:pack 1:embed_ln 2:QKV 3:ATTENTION (ncu capture slot)
    pack_qkv_kernel<<<2048, 256>>>(Wq, Wk, Wv);
    embed_ln_kernel<<<BT, 256>>>(idx, tok_emb, pos_emb, ln1_g, ln1_b);

    for (int l = 0; l < LL; l++) {
        if (l > 0)
            layernorm_kernel<<<BT, 256>>>(xp, ln1_g + l*CC, ln1_b + l*CC, hp);

        // qkv = h @ Wqkv[l]    [2048,768]x[768,2304]
        gemm_tf32_kernel<128,false,false,false,false>
            <<<dim3(BT/128, QKVN/128), 256>>>(
            hp, wqkvp + (long)l*CC*QKVN, nullptr, nullptr, qkvp, BT, QKVN, CC);

        flash_attn_kernel<<<dim3(TT/TQ, BB*HH), 128>>>(qkvp, attnp);

        if (l == 0) {
            round_copy2_kernel<<<2048, 256>>>(Wproj, wprojp, (long)LL*CC*CC,
                                              W1,    w1p,    (long)LL*CC*HID);
            round_copy2_kernel<<<4096, 256>>>(W2,    w2p,    (long)LL*HID*CC,
                                              Wlm,   wlmp,   (long)CC*VV);
        }

        // x = x + attn @ Wproj[l] + bproj[l]   (BN=64: grid 16x12)
        gemm_tf32_kernel<64,true,false,true,false>
            <<<dim3(BT/128, CC/64), 256>>>(
            attnp, wprojp + (long)l*CC*CC, bproj + l*CC, xp, xp, BT, CC, CC);

        layernorm_kernel<<<BT, 256>>>(xp, ln2_g + l*CC, ln2_b + l*CC, hp);

        // hid = relu(h @ W1[l] + b1[l])  (rounded output: feeds next GEMM)
        gemm_tf32_kernel<128,true,true,false,true>
            <<<dim3(BT/128, HID/128), 256>>>(
            hp, w1p + (long)l*CC*HID, b1 + (long)l*HID, nullptr, hidp, BT, HID, CC);

        // x = x + hid @ W2[l] + b2[l]  (BN=64); last layer fuses tf32-round
        if (l == LL-1) {
            gemm_tf32_kernel<64,true,false,true,true>
                <<<dim3(BT/128, CC/64), 256>>>(
                hidp, w2p + (long)l*HID*CC, b2 + l*CC, xp, hp, BT, CC, HID);
        } else {
            gemm_tf32_kernel<64,true,false,true,false>
                <<<dim3(BT/128, CC/64), 256>>>(
                hidp, w2p + (long)l*HID*CC, b2 + l*CC, xp, xp, BT, CC, HID);
        }
    }

    // logits = x @ Wlm + blm -> d_out
    gemm_tf32_kernel<128,true,false,false,false>
        <<<dim3(BT/128, VV/128), 256>>>(
        hp, wlmp, blm, nullptr, out, BT, VV, CC);

    loss_rows_kernel<<<BT, 256>>>(out, targets);
    if (out_size >= BT*VV + 1) {
        loss_reduce_kernel<<<1, 256>>>(out + (long)BT*VV);
    } else if (out_size == 1) {
        loss_reduce_kernel<<<1, 256>>>(out);
    }
}

// round 16
// speedup vs baseline: 1.0361x; 1.0361x over previous
#include <cuda_runtime.h>
#include <cuda_bf16.h>
#include <cstdint>

// Problem constants
#define BB 2
#define TT 1024
#define CC 768
#define HH 12
#define DH 64
#define LL 4
#define HID 3072
#define VV 32000
#define BT (BB*TT)          // 2048
#define QKVN (3*CC)         // 2304

// ---------------- scratch (device globals; no cudaMalloc allowed) ----------
__device__ float g_x[BT*CC];          // residual stream
__device__ float g_h[BT*CC];          // layernorm output / rounded x copy
__device__ float g_qkv[BT*QKVN];      // fused qkv output
__device__ float g_attn[BT*CC];       // attention output (concat heads)
__device__ float g_hid[BT*HID];       // MLP hidden
__device__ float g_wqkv[LL*CC*QKVN];  // packed+rounded qkv weights [k][n]
__device__ float g_wproj[LL*CC*CC];   // rounded
__device__ float g_w1[LL*CC*HID];     // rounded
__device__ float g_w2[LL*HID*CC];     // rounded
__device__ float g_wlm[CC*VV];        // rounded
__device__ float g_rowloss[BT];       // per-row -logp[target]

__device__ __forceinline__ uint32_t f2tf32(float f) {
    uint32_t u;
    asm("cvt.rna.tf32.f32 %0, %1;" : "=r"(u) : "f"(f));
    return u;
}
__device__ __forceinline__ float tf32r(float f) {
    return __uint_as_float(f2tf32(f));
}

// ---- packed f32x2 helpers (base sm_100-family PTX, no 'a' features) -------
#define FMA2(d, a, b) asm volatile("fma.rn.f32x2 %0, %1, %2, %0;" : "+l"(d) : "l"(a), "l"(b))
#define MUL2(d, a, b) asm("mul.rn.f32x2 %0, %1, %2;" : "=l"(d) : "l"(a), "l"(b))
#define ADD2(d, a, b) asm("add.rn.f32x2 %0, %1, %2;" : "=l"(d) : "l"(a), "l"(b))
#define PACK2(d, lo, hi) asm("mov.b64 %0, {%1, %2};" : "=l"(d) : "r"(__float_as_uint(lo)), "r"(__float_as_uint(hi)))
#define UNPACK2(lo, hi, d) do { uint32_t _ul, _uh;                          \
    asm("mov.b64 {%0, %1}, %2;" : "=r"(_ul), "=r"(_uh) : "l"(d));           \
    lo = __uint_as_float(_ul); hi = __uint_as_float(_uh); } while (0)
#define LDS2B64(a, b, addr) asm volatile("ld.shared.v2.b64 {%0, %1}, [%2];" : "=l"(a), "=l"(b) : "r"(addr))

#define CP16(dst, src) asm volatile("cp.async.cg.shared.global [%0], [%1], 16;" :: "r"(dst), "l"(src))

// ---------------- weight packing: Wq/Wk/Wv [L,H,C,DH] -> [L][C][3C] (tf32) -
__global__ void pack_qkv_kernel(const float* __restrict__ Wq,
                                const float* __restrict__ Wk,
                                const float* __restrict__ Wv) {
    const long total = (long)LL * CC * QKVN;
    for (long i = (long)blockIdx.x * blockDim.x + threadIdx.x; i < total;
         i += (long)gridDim.x * blockDim.x) {
        int n = (int)(i % QKVN);
        long r = i / QKVN;
        int k = (int)(r % CC);
        int l = (int)(r / CC);
        const float* W; int nn = n;
        if (n < CC)           { W = Wq; }
        else if (n < 2*CC)    { W = Wk; nn = n - CC; }
        else                  { W = Wv; nn = n - 2*CC; }
        int h = nn >> 6, d = nn & 63;
        g_wqkv[i] = tf32r(W[(((long)l*HH + h)*CC + k)*DH + d]);
    }
}

// ---------------- dual tf32 round-copy (fewer launches) --------------------
__global__ void round_copy2_kernel(const float* __restrict__ s0, float* __restrict__ d0, long n0,
                                   const float* __restrict__ s1, float* __restrict__ d1, long n1) {
    const long stride = (long)gridDim.x * blockDim.x;
    for (long i = (long)blockIdx.x * blockDim.x + threadIdx.x; i < n0; i += stride)
        d0[i] = tf32r(s0[i]);
    for (long i = (long)blockIdx.x * blockDim.x + threadIdx.x; i < n1; i += stride)
        d1[i] = tf32r(s1[i]);
}

// ---------------- fused embed + layer-0 ln1 --------------------------------
__global__ void embed_ln_kernel(const int* __restrict__ idx,
                                const float* __restrict__ tok,
                                const float* __restrict__ pos,
                                const float* __restrict__ g,
                                const float* __restrict__ b) {
    __shared__ float rs[256], rs2[256];
    const int row = blockIdx.x;
    const int t = row % TT;
    const float* tr = tok + (long)idx[row]*CC;
    const float* pr = pos + (long)t*CC;
    float vals[CC/256];
    float s = 0.f, s2 = 0.f;
    #pragma unroll
    for (int i = 0; i < CC/256; i++) {
        int c = threadIdx.x + i*256;
        float v = tr[c] + pr[c];
        vals[i] = v;
        g_x[(long)row*CC + c] = v;
        s += v; s2 += v*v;
    }
    rs[threadIdx.x] = s; rs2[threadIdx.x] = s2;
    __syncthreads();
    for (int o = 128; o > 0; o >>= 1) {
        if (threadIdx.x < o) {
            rs[threadIdx.x]  += rs[threadIdx.x + o];
            rs2[threadIdx.x] += rs2[threadIdx.x + o];
        }
        __syncthreads();
    }
    float mean = rs[0] * (1.f/CC);
    float var  = rs2[0] * (1.f/CC) - mean*mean;
    float inv  = rsqrtf(var + 1e-5f);
    #pragma unroll
    for (int i = 0; i < CC/256; i++) {
        int c = threadIdx.x + i*256;
        g_h[(long)row*CC + c] = tf32r((vals[i] - mean) * inv * g[c] + b[c]);
    }
}

// ---------------- layernorm (rounded output) -------------------------------
__global__ void layernorm_kernel(const float* __restrict__ x,
                                 const float* __restrict__ g,
                                 const float* __restrict__ b,
                                 float* __restrict__ y) {
    __shared__ float rs[256], rs2[256];
    int row = blockIdx.x;
    const float* xr = x + (long)row*CC;
    float s = 0.f, s2 = 0.f;
    for (int c = threadIdx.x; c < CC; c += 256) {
        float v = xr[c];
        s += v; s2 += v*v;
    }
    rs[threadIdx.x] = s; rs2[threadIdx.x] = s2;
    __syncthreads();
    for (int o = 128; o > 0; o >>= 1) {
        if (threadIdx.x < o) {
            rs[threadIdx.x]  += rs[threadIdx.x + o];
            rs2[threadIdx.x] += rs2[threadIdx.x + o];
        }
        __syncthreads();
    }
    float mean = rs[0] * (1.f/CC);
    float var  = rs2[0] * (1.f/CC) - mean*mean;
    float inv  = rsqrtf(var + 1e-5f);
    for (int c = threadIdx.x; c < CC; c += 256) {
        y[(long)row*CC + c] = tf32r((xr[c] - mean) * inv * g[c] + b[c]);
    }
}

// ---------------- TF32 tensor-core GEMM, cp.async 4-stage, kc-staggered ----
#define ASTRIDE 20
#define STAGES 4

#define MMA_TF32(acc, af, bf)                                              \
    asm volatile(                                                          \
        "mma.sync.aligned.m16n8k8.row.col.f32.tf32.tf32.f32 "              \
        "{%0,%1,%2,%3},{%4,%5,%6,%7},{%8,%9},{%0,%1,%2,%3};"               \
        : "+f"((acc)[0]), "+f"((acc)[1]), "+f"((acc)[2]), "+f"((acc)[3])   \
        : "r"((af)[0]), "r"((af)[1]), "r"((af)[2]), "r"((af)[3]),          \
          "r"((bf)[0]), "r"((bf)[1]))

template<int BN, bool BIAS, bool RELU, bool RES, bool ROUND>
__global__ void __launch_bounds__(256, 2)
gemm_tf32_kernel(const float* __restrict__ A, const float* __restrict__ B,
                 const float* __restrict__ bias, const float* __restrict__ res,
                 float* __restrict__ C, int M, int N, int K) {
    constexpr int BSTRIDE = BN + 8;
    constexpr int NI = BN / 16;
    constexpr int BTPR = BN / 4;
    constexpr int BRPP = 256 / BTPR;
    constexpr int BPASS = 16 / BRPP;
    __shared__ float As[STAGES][128*ASTRIDE];
    __shared__ float Bs[STAGES][16*BSTRIDE];
    const int tid  = threadIdx.x;
    const int wid  = tid >> 5;
    const int lane = tid & 31;
    const int warpM = wid & 3;
    const int warpN = wid >> 2;
    const int gr = lane >> 2;
    const int gc = lane & 3;
    const int m0 = blockIdx.x * 128;
    const int n0 = blockIdx.y * BN;
    const int kcFirst = (wid & 1) << 3;
    const int kcSecond = kcFirst ^ 8;

    float acc[2][NI][4];
    #pragma unroll
    for (int mi = 0; mi < 2; mi++)
        #pragma unroll
        for (int ni = 0; ni < NI; ni++)
            #pragma unroll
            for (int j = 0; j < 4; j++) acc[mi][ni][j] = 0.f;

    const int aRow = tid >> 2;
    const int aCol = (tid & 3) << 2;
    const int bRow = tid / BTPR;
    const int bCol = (tid % BTPR) * 4;

    const float* Ab = A + (long)m0*K;
    const float* Bb = B + n0;
    const int nIter = K >> 4;

    #define ISSUE(it, stg) do {                                            \
        const float* Ag = Ab + ((it) << 4);                                \
        _Pragma("unroll")                                                  \
        for (int r = 0; r < 2; r++) {                                      \
            int row = aRow + r*64;                                         \
            uint32_t d_ = (uint32_t)__cvta_generic_to_shared(              \
                &As[stg][row*ASTRIDE + aCol]);                             \
            CP16(d_, Ag + (long)row*K + aCol);                             \
        }                                                                  \
        const float* Bg = Bb + (long)((it) << 4)*N;                        \
        _Pragma("unroll")                                                  \
        for (int r = 0; r < BPASS; r++) {                                  \
            int krow = bRow + r*BRPP;                                      \
            uint32_t d_ = (uint32_t)__cvta_generic_to_shared(              \
                &Bs[stg][krow*BSTRIDE + bCol]);                            \
            CP16(d_, Bg + (long)krow*N + bCol);                            \
        }                                                                  \
        asm volatile("cp.async.commit_group;");                            \
    } while (0)

    #define DO_KC(kc, stg) do {                                            \
        uint32_t af[2][4];                                                 \
        _Pragma("unroll")                                                  \
        for (int mi = 0; mi < 2; mi++) {                                   \
            int row = warpM*32 + mi*16 + gr;                               \
            af[mi][0] = __float_as_uint(As[stg][row*ASTRIDE + (kc) + gc]); \
            af[mi][1] = __float_as_uint(As[stg][(row+8)*ASTRIDE + (kc) + gc]); \
            af[mi][2] = __float_as_uint(As[stg][row*ASTRIDE + (kc) + gc + 4]); \
            af[mi][3] = __float_as_uint(As[stg][(row+8)*ASTRIDE + (kc) + gc + 4]); \
        }                                                                  \
        uint32_t bf[NI][2];                                                \
        _Pragma("unroll")                                                  \
        for (int ni = 0; ni < NI; ni++) {                                  \
            int col = warpN*(BN/2) + ni*8 + gr;                            \
            bf[ni][0] = __float_as_uint(Bs[stg][((kc)+gc)*BSTRIDE + col]); \
            bf[ni][1] = __float_as_uint(Bs[stg][((kc)+gc+4)*BSTRIDE + col]); \
        }                                                                  \
        _Pragma("unroll")                                                  \
        for (int mi = 0; mi < 2; mi++)                                     \
            _Pragma("unroll")                                              \
            for (int ni = 0; ni < NI; ni++)                                \
                MMA_TF32(acc[mi][ni], af[mi], bf[ni]);                     \
    } while (0)

    ISSUE(0, 0); ISSUE(1, 1); ISSUE(2, 2);

    for (int it = 0; it < nIter; it++) {
        const int stg = it & (STAGES-1);
        if (it + 2 < nIter)      asm volatile("cp.async.wait_group 2;");
        else if (it + 1 < nIter) asm volatile("cp.async.wait_group 1;");
        else                     asm volatile("cp.async.wait_group 0;");
        __syncthreads();

        DO_KC(kcFirst, stg);
        if (it + 3 < nIter) ISSUE(it + 3, (it + 3) & (STAGES-1));
        DO_KC(kcSecond, stg);
    }
    #undef DO_KC
    #undef ISSUE

    #pragma unroll
    for (int mi = 0; mi < 2; mi++) {
        #pragma unroll
        for (int rr = 0; rr < 2; rr++) {
            long row = m0 + warpM*32 + mi*16 + gr + rr*8;
            #pragma unroll
            for (int ni = 0; ni < NI; ni++) {
                int col = n0 + warpN*(BN/2) + ni*8 + gc*2;
                float v0 = acc[mi][ni][rr*2+0];
                float v1 = acc[mi][ni][rr*2+1];
                if (BIAS) { v0 += bias[col]; v1 += bias[col+1]; }
                if (RES)  {
                    float2 rv = *(const float2*)(res + row*N + col);
                    v0 += rv.x; v1 += rv.y;
                }
                if (RELU) { v0 = fmaxf(v0, 0.f); v1 = fmaxf(v1, 0.f); }
                if (ROUND){ v0 = tf32r(v0); v1 = tf32r(v1); }
                float2 ov; ov.x = v0; ov.y = v1;
                *(float2*)(C + row*N + col) = ov;
            }
        }
    }
}

// ---- flash attention, 2-way split-K, f32x2 math (R12-best) + occ=3 force --
#define TQ 64
#define TS 16
__global__ void __launch_bounds__(128, 3)
flash_attn_kernel(const float* __restrict__ qkv, float* __restrict__ out) {
    __shared__ float KV[2][2][TS*DH];   // [k/v][half][s*DH+d]
    __shared__ float ml[2][TQ];
    const int q0 = (gridDim.x - 1 - blockIdx.x) * TQ;  // longest first
    const int bh = blockIdx.y;
    const int b  = bh / HH;
    const int h  = bh % HH;
    const int tid  = threadIdx.x;
    const int tq   = tid & 63;
    const int half = tid >> 6;
    const int t = q0 + tq;
    const float* base = qkv + (long)b*TT*QKVN;

    const uint32_t ksm = (uint32_t)__cvta_generic_to_shared(&KV[0][half][0]);
    const uint32_t vsm = (uint32_t)__cvta_generic_to_shared(&KV[1][half][0]);

    // q packed into f32x2 pairs
    uint64_t q2[DH/2];
    {
        const float4* qr = (const float4*)(base + (long)t*QKVN + h*DH);
        #pragma unroll
        for (int j = 0; j < DH/4; j++) {
            float4 v = qr[j];
            PACK2(q2[2*j+0], v.x, v.y);
            PACK2(q2[2*j+1], v.z, v.w);
        }
    }
    uint64_t acc2[DH/2];
    #pragma unroll
    for (int j = 0; j < DH/2; j++) acc2[j] = 0ull;
    float m = -1e30f, l = 0.f;

    const int nT = (q0 + TQ) / TS;
    const int nHalf = nT >> 1;
    const int tile0 = half * nHalf;

    for (int jt = 0; jt < nHalf; jt++) {
        const int s0 = (tile0 + jt) * TS;
        __syncthreads();
        #pragma unroll
        for (int i = 0; i < 4; i++) {
            int idx = tq + i*64;
            int s  = idx >> 4;
            int d4 = (idx & 15) << 2;
            const float* kp = base + (long)(s0+s)*QKVN + CC + h*DH + d4;
            *(float4*)&KV[0][half][s*DH + d4] = *(const float4*)kp;
            *(float4*)&KV[1][half][s*DH + d4] = *(const float4*)(kp + CC);
        }
        __syncthreads();

        float sc[TS];
        float tmax = -1e30f;
        #pragma unroll
        for (int s = 0; s < TS; s++) {
            uint32_t ka = ksm + s*DH*4;
            uint64_t d0 = 0ull, d1 = 0ull, d2 = 0ull, d3 = 0ull;
            #pragma unroll
            for (int j = 0; j < DH/2; j += 4) {
                uint64_t k0, k1, k2, k3;
                LDS2B64(k0, k1, ka + j*8);
                LDS2B64(k2, k3, ka + (j+2)*8);
                FMA2(d0, q2[j+0], k0);
                FMA2(d1, q2[j+1], k1);
                FMA2(d2, q2[j+2], k2);
                FMA2(d3, q2[j+3], k3);
            }
            ADD2(d0, d0, d1); ADD2(d2, d2, d3); ADD2(d0, d0, d2);
            float lo, hi; UNPACK2(lo, hi, d0);
            float d = lo + hi;
            sc[s] = (s0 + s <= t) ? d * 0.125f : -1e30f;
            tmax = fmaxf(tmax, sc[s]);
        }
        if (tmax > -1e29f) {
            float m_new = fmaxf(m, tmax);
            float alpha = __expf(m - m_new);
            l *= alpha;
            uint64_t a2; PACK2(a2, alpha, alpha);
            #pragma unroll
            for (int j = 0; j < DH/2; j++) MUL2(acc2[j], acc2[j], a2);
            #pragma unroll
            for (int s = 0; s < TS; s++) {
                float p = (sc[s] > -1e29f) ? __expf(sc[s] - m_new) : 0.f;
                l += p;
                uint64_t p2; PACK2(p2, p, p);
                uint32_t va = vsm + s*DH*4;
                #pragma unroll
                for (int j = 0; j < DH/2; j += 2) {
                    uint64_t v0, v1;
                    LDS2B64(v0, v1, va + j*8);
                    FMA2(acc2[j+0], p2, v0);
                    FMA2(acc2[j+1], p2, v1);
                }
            }
            m = m_new;
        }
    }

    float acc[DH];
    #pragma unroll
    for (int j = 0; j < DH/2; j++) {
        float lo, hi; UNPACK2(lo, hi, acc2[j]);
        acc[2*j] = lo; acc[2*j+1] = hi;
    }

    __syncthreads();
    float* xch = (float*)KV;
    if (half == 1) {
        ml[0][tq] = m; ml[1][tq] = l;
        #pragma unroll
        for (int j = 0; j < DH; j++)
            xch[tq*DH + ((j + tq) & 63)] = acc[j];
    }
    __syncthreads();
    if (half == 0) {
        float m1 = ml[0][tq], l1 = ml[1][tq];
        float ms = fmaxf(m, m1);
        float a0 = __expf(m - ms);
        float a1 = __expf(m1 - ms);
        float inv = 1.0f / (l*a0 + l1*a1);
        float* o = out + ((long)b*TT + t)*CC + h*DH;
        #pragma unroll
        for (int j = 0; j < DH; j += 4) {
            float4 v;
            v.x = tf32r((acc[j+0]*a0 + xch[tq*DH + ((j+0+tq)&63)]*a1) * inv);
            v.y = tf32r((acc[j+1]*a0 + xch[tq*DH + ((j+1+tq)&63)]*a1) * inv);
            v.z = tf32r((acc[j+2]*a0 + xch[tq*DH + ((j+2+tq)&63)]*a1) * inv);
            v.w = tf32r((acc[j+3]*a0 + xch[tq*DH + ((j+3+tq)&63)]*a1) * inv);
            *(float4*)(o + j) = v;
        }
    }
}

// ---------------- cross-entropy: single-pass online softmax (float4) -------
__global__ void loss_rows_kernel(const float* __restrict__ logits,
                                 const int* __restrict__ targets) {
    __shared__ float sm[256], ss[256];
    const int row = blockIdx.x;
    const float4* lr4 = (const float4*)(logits + (long)row*VV);
    float m = -1e30f, s = 0.f;
    for (int c4 = threadIdx.x; c4 < VV/4; c4 += 256) {
        float4 v4 = lr4[c4];
        float vm = fmaxf(fmaxf(v4.x, v4.y), fmaxf(v4.z, v4.w));
        if (vm <= m) {
            s += __expf(v4.x - m) + __expf(v4.y - m)
               + __expf(v4.z - m) + __expf(v4.w - m);
        } else {
            s = s*__expf(m - vm)
              + __expf(v4.x - vm) + __expf(v4.y - vm)
              + __expf(v4.z - vm) + __expf(v4.w - vm);
            m = vm;
        }
    }
    sm[threadIdx.x] = m; ss[threadIdx.x] = s;
    __syncthreads();
    for (int o = 128; o > 0; o >>= 1) {
        if (threadIdx.x < o) {
            float m2 = sm[threadIdx.x+o], s2 = ss[threadIdx.x+o];
            float mm = fmaxf(sm[threadIdx.x], m2);
            ss[threadIdx.x] = ss[threadIdx.x]*__expf(sm[threadIdx.x]-mm)
                            + s2*__expf(m2-mm);
            sm[threadIdx.x] = mm;
        }
        __syncthreads();
    }
    if (threadIdx.x == 0) {
        float lse = sm[0] + logf(ss[0]);
        g_rowloss[row] = lse - logits[(long)row*VV + targets[row]];
    }
}

__global__ void loss_reduce_kernel(float* __restrict__ out) {
    __shared__ float red[256];
    float s = 0.f;
    for (int i = threadIdx.x; i < BT; i += 256) s += g_rowloss[i];
    red[threadIdx.x] = s; __syncthreads();
    for (int o = 128; o > 0; o >>= 1) {
        if (threadIdx.x < o) red[threadIdx.x] += red[threadIdx.x+o];
        __syncthreads();
    }
    if (threadIdx.x == 0) *out = red[0] * (1.0f/BT);
}

// ---------------- driver ----------------------------------------------------
extern "C" void kernel_launch(void* const* d_in, const int* in_sizes, int n_in,
                              void* d_out, int out_size) {
    const int*   idx     = (const int*)  d_in[0];
    const int*   targets = (const int*)  d_in[1];
    const float* tok_emb = (const float*)d_in[2];
    const float* pos_emb = (const float*)d_in[3];
    const float* Wq      = (const float*)d_in[4];
    const float* Wk      = (const float*)d_in[5];
    const float* Wv      = (const float*)d_in[6];
    const float* Wproj   = (const float*)d_in[7];
    const float* bproj   = (const float*)d_in[8];
    const float* ln1_g   = (const float*)d_in[9];
    const float* ln1_b   = (const float*)d_in[10];
    const float* ln2_g   = (const float*)d_in[11];
    const float* ln2_b   = (const float*)d_in[12];
    const float* W1      = (const float*)d_in[13];
    const float* b1      = (const float*)d_in[14];
    const float* W2      = (const float*)d_in[15];
    const float* b2      = (const float*)d_in[16];
    const float* Wlm     = (const float*)d_in[17];
    const float* blm     = (const float*)d_in[18];
    float* out = (float*)d_out;

    float* xp;    cudaGetSymbolAddress((void**)&xp,    g_x);
    float* hp;    cudaGetSymbolAddress((void**)&hp,    g_h);
    float* qkvp;  cudaGetSymbolAddress((void**)&qkvp,  g_qkv);
    float* attnp; cudaGetSymbolAddress((void**)&attnp, g_attn);
    float* hidp;  cudaGetSymbolAddress((void**)&hidp,  g_hid);
    float* wqkvp; cudaGetSymbolAddress((void**)&wqkvp, g_wqkv);
    float* wprojp;cudaGetSymbolAddress((void**)&wprojp,g_wproj);
    float* w1p;   cudaGetSymbolAddress((void**)&w1p,   g_w1);
    float* w2p;   cudaGetSymbolAddress((void**)&w2p,   g_w2);
    float* wlmp;  cudaGetSymbolAddress((void**)&wlmp,  g_wlm);

    // Launch order: 0:pack 1:embed_ln 2:QKV 3:ATTENTION (ncu capture slot)
    pack_qkv_kernel<<<2048, 256>>>(Wq, Wk, Wv);
    embed_ln_kernel<<<BT, 256>>>(idx, tok_emb, pos_emb, ln1_g, ln1_b);

    for (int l = 0; l < LL; l++) {
        if (l > 0)
            layernorm_kernel<<<BT, 256>>>(xp, ln1_g + l*CC, ln1_b + l*CC, hp);

        // qkv = h @ Wqkv[l]    [2048,768]x[768,2304]
        gemm_tf32_kernel<128,false,false,false,false>
            <<<dim3(BT/128, QKVN/128), 256>>>(
            hp, wqkvp + (long)l*CC*QKVN, nullptr, nullptr, qkvp, BT, QKVN, CC);

        flash_attn_kernel<<<dim3(TT/TQ, BB*HH), 128>>>(qkvp, attnp);

        if (l == 0) {
            round_copy2_kernel<<<2048, 256>>>(Wproj, wprojp, (long)LL*CC*CC,
                                              W1,    w1p,    (long)LL*CC*HID);
            round_copy2_kernel<<<4096, 256>>>(W2,    w2p,    (long)LL*HID*CC,
                                              Wlm,   wlmp,   (long)CC*VV);
        }

        // x = x + attn @ Wproj[l] + bproj[l]   (BN=64: grid 16x12)
        gemm_tf32_kernel<64,true,false,true,false>
            <<<dim3(BT/128, CC/64), 256>>>(
            attnp, wprojp + (long)l*CC*CC, bproj + l*CC, xp, xp, BT, CC, CC);

        layernorm_kernel<<<BT, 256>>>(xp, ln2_g + l*CC, ln2_b + l*CC, hp);

        // hid = relu(h @ W1[l] + b1[l])  (rounded output: feeds next GEMM)
        gemm_tf32_kernel<128,true,true,false,true>
            <<<dim3(BT/128, HID/128), 256>>>(
            hp, w1p + (long)l*CC*HID, b1 + (long)l*HID, nullptr, hidp, BT, HID, CC);

        // x = x + hid @ W2[l] + b2[l]  (BN=64); last layer fuses tf32-round
        if (l == LL-1) {
            gemm_tf32_kernel<64,true,false,true,true>
                <<<dim3(BT/128, CC/64), 256>>>(
                hidp, w2p + (long)l*HID*CC, b2 + l*CC, xp, hp, BT, CC, HID);
        } else {
            gemm_tf32_kernel<64,true,false,true,false>
                <<<dim3(BT/128, CC/64), 256>>>(
                hidp, w2p + (long)l*HID*CC, b2 + l*CC, xp, xp, BT, CC, HID);
        }
    }

    // logits = x @ Wlm + blm -> d_out
    gemm_tf32_kernel<128,true,false,false,false>
        <<<dim3(BT/128, VV/128), 256>>>(
        hp, wlmp, blm, nullptr, out, BT, VV, CC);

    loss_rows_kernel<<<BT, 256>>>(out, targets);
    if (out_size >= BT*VV + 1) {
        loss_reduce_kernel<<<1, 256>>>(out + (long)BT*VV);
    } else if (out_size == 1) {
        loss_reduce_kernel<<<1, 256>>>(out);
    }
}

// round 17
// speedup vs baseline: 1.1625x; 1.1219x over previous
#include <cuda_runtime.h>
#include <cuda_bf16.h>
#include <cstdint>

// Problem constants
#define BB 2
#define TT 1024
#define CC 768
#define HH 12
#define DH 64
#define LL 4
#define HID 3072
#define VV 32000
#define BT (BB*TT)          // 2048
#define QKVN (3*CC)         // 2304

// ---------------- scratch (device globals; no cudaMalloc allowed) ----------
__device__ float g_x[BT*CC];          // residual stream
__device__ float g_h[BT*CC];          // layernorm output / rounded x copy
__device__ float g_qkv[BT*QKVN];      // fused qkv output
__device__ float g_attn[BT*CC];       // attention output (concat heads)
__device__ float g_hid[BT*HID];       // MLP hidden
__device__ float g_wqkv[LL*CC*QKVN];  // packed+rounded qkv weights [k][n]
__device__ float g_wproj[LL*CC*CC];   // rounded
__device__ float g_w1[LL*CC*HID];     // rounded
__device__ float g_w2[LL*HID*CC];     // rounded
__device__ float g_wlm[CC*VV];        // rounded
__device__ float g_rowloss[BT];       // per-row -logp[target]

__device__ __forceinline__ uint32_t f2tf32(float f) {
    uint32_t u;
    asm("cvt.rna.tf32.f32 %0, %1;" : "=r"(u) : "f"(f));
    return u;
}
__device__ __forceinline__ float tf32r(float f) {
    return __uint_as_float(f2tf32(f));
}

// ---- packed f32x2 helpers (base sm_100-family PTX, no 'a' features) -------
#define FMA2(d, a, b) asm volatile("fma.rn.f32x2 %0, %1, %2, %0;" : "+l"(d) : "l"(a), "l"(b))
#define MUL2(d, a, b) asm("mul.rn.f32x2 %0, %1, %2;" : "=l"(d) : "l"(a), "l"(b))
#define ADD2(d, a, b) asm("add.rn.f32x2 %0, %1, %2;" : "=l"(d) : "l"(a), "l"(b))
#define PACK2(d, lo, hi) asm("mov.b64 %0, {%1, %2};" : "=l"(d) : "r"(__float_as_uint(lo)), "r"(__float_as_uint(hi)))
#define UNPACK2(lo, hi, d) do { uint32_t _ul, _uh;                          \
    asm("mov.b64 {%0, %1}, %2;" : "=r"(_ul), "=r"(_uh) : "l"(d));           \
    lo = __uint_as_float(_ul); hi = __uint_as_float(_uh); } while (0)
#define LDS2B64(a, b, addr) asm volatile("ld.shared.v2.b64 {%0, %1}, [%2];" : "=l"(a), "=l"(b) : "r"(addr))

#define CP16(dst, src) asm volatile("cp.async.cg.shared.global [%0], [%1], 16;" :: "r"(dst), "l"(src))

// ---------------- weight packing: Wq/Wk/Wv [L,H,C,DH] -> [L][C][3C] (tf32) -
__global__ void pack_qkv_kernel(const float* __restrict__ Wq,
                                const float* __restrict__ Wk,
                                const float* __restrict__ Wv) {
    const long total = (long)LL * CC * QKVN;
    for (long i = (long)blockIdx.x * blockDim.x + threadIdx.x; i < total;
         i += (long)gridDim.x * blockDim.x) {
        int n = (int)(i % QKVN);
        long r = i / QKVN;
        int k = (int)(r % CC);
        int l = (int)(r / CC);
        const float* W; int nn = n;
        if (n < CC)           { W = Wq; }
        else if (n < 2*CC)    { W = Wk; nn = n - CC; }
        else                  { W = Wv; nn = n - 2*CC; }
        int h = nn >> 6, d = nn & 63;
        g_wqkv[i] = tf32r(W[(((long)l*HH + h)*CC + k)*DH + d]);
    }
}

// ---------------- dual tf32 round-copy (fewer launches) --------------------
__global__ void round_copy2_kernel(const float* __restrict__ s0, float* __restrict__ d0, long n0,
                                   const float* __restrict__ s1, float* __restrict__ d1, long n1) {
    const long stride = (long)gridDim.x * blockDim.x;
    for (long i = (long)blockIdx.x * blockDim.x + threadIdx.x; i < n0; i += stride)
        d0[i] = tf32r(s0[i]);
    for (long i = (long)blockIdx.x * blockDim.x + threadIdx.x; i < n1; i += stride)
        d1[i] = tf32r(s1[i]);
}

// ---------------- fused embed + layer-0 ln1 --------------------------------
__global__ void embed_ln_kernel(const int* __restrict__ idx,
                                const float* __restrict__ tok,
                                const float* __restrict__ pos,
                                const float* __restrict__ g,
                                const float* __restrict__ b) {
    __shared__ float rs[256], rs2[256];
    const int row = blockIdx.x;
    const int t = row % TT;
    const float* tr = tok + (long)idx[row]*CC;
    const float* pr = pos + (long)t*CC;
    float vals[CC/256];
    float s = 0.f, s2 = 0.f;
    #pragma unroll
    for (int i = 0; i < CC/256; i++) {
        int c = threadIdx.x + i*256;
        float v = tr[c] + pr[c];
        vals[i] = v;
        g_x[(long)row*CC + c] = v;
        s += v; s2 += v*v;
    }
    rs[threadIdx.x] = s; rs2[threadIdx.x] = s2;
    __syncthreads();
    for (int o = 128; o > 0; o >>= 1) {
        if (threadIdx.x < o) {
            rs[threadIdx.x]  += rs[threadIdx.x + o];
            rs2[threadIdx.x] += rs2[threadIdx.x + o];
        }
        __syncthreads();
    }
    float mean = rs[0] * (1.f/CC);
    float var  = rs2[0] * (1.f/CC) - mean*mean;
    float inv  = rsqrtf(var + 1e-5f);
    #pragma unroll
    for (int i = 0; i < CC/256; i++) {
        int c = threadIdx.x + i*256;
        g_h[(long)row*CC + c] = tf32r((vals[i] - mean) * inv * g[c] + b[c]);
    }
}

// ---------------- layernorm (rounded output) -------------------------------
__global__ void layernorm_kernel(const float* __restrict__ x,
                                 const float* __restrict__ g,
                                 const float* __restrict__ b,
                                 float* __restrict__ y) {
    __shared__ float rs[256], rs2[256];
    int row = blockIdx.x;
    const float* xr = x + (long)row*CC;
    float s = 0.f, s2 = 0.f;
    for (int c = threadIdx.x; c < CC; c += 256) {
        float v = xr[c];
        s += v; s2 += v*v;
    }
    rs[threadIdx.x] = s; rs2[threadIdx.x] = s2;
    __syncthreads();
    for (int o = 128; o > 0; o >>= 1) {
        if (threadIdx.x < o) {
            rs[threadIdx.x]  += rs[threadIdx.x + o];
            rs2[threadIdx.x] += rs2[threadIdx.x + o];
        }
        __syncthreads();
    }
    float mean = rs[0] * (1.f/CC);
    float var  = rs2[0] * (1.f/CC) - mean*mean;
    float inv  = rsqrtf(var + 1e-5f);
    for (int c = threadIdx.x; c < CC; c += 256) {
        y[(long)row*CC + c] = tf32r((xr[c] - mean) * inv * g[c] + b[c]);
    }
}

// ---------------- TF32 tensor-core GEMM, cp.async 4-stage, kc-staggered ----
#define ASTRIDE 20
#define STAGES 4

#define MMA_TF32(acc, af, bf)                                              \
    asm volatile(                                                          \
        "mma.sync.aligned.m16n8k8.row.col.f32.tf32.tf32.f32 "              \
        "{%0,%1,%2,%3},{%4,%5,%6,%7},{%8,%9},{%0,%1,%2,%3};"               \
        : "+f"((acc)[0]), "+f"((acc)[1]), "+f"((acc)[2]), "+f"((acc)[3])   \
        : "r"((af)[0]), "r"((af)[1]), "r"((af)[2]), "r"((af)[3]),          \
          "r"((bf)[0]), "r"((bf)[1]))

template<int BN, bool BIAS, bool RELU, bool RES, bool ROUND>
__global__ void __launch_bounds__(256, 2)
gemm_tf32_kernel(const float* __restrict__ A, const float* __restrict__ B,
                 const float* __restrict__ bias, const float* __restrict__ res,
                 float* __restrict__ C, int M, int N, int K) {
    constexpr int BSTRIDE = BN + 8;
    constexpr int NI = BN / 16;
    constexpr int BTPR = BN / 4;
    constexpr int BRPP = 256 / BTPR;
    constexpr int BPASS = 16 / BRPP;
    __shared__ float As[STAGES][128*ASTRIDE];
    __shared__ float Bs[STAGES][16*BSTRIDE];
    const int tid  = threadIdx.x;
    const int wid  = tid >> 5;
    const int lane = tid & 31;
    const int warpM = wid & 3;
    const int warpN = wid >> 2;
    const int gr = lane >> 2;
    const int gc = lane & 3;
    const int m0 = blockIdx.x * 128;
    const int n0 = blockIdx.y * BN;
    const int kcFirst = (wid & 1) << 3;
    const int kcSecond = kcFirst ^ 8;

    float acc[2][NI][4];
    #pragma unroll
    for (int mi = 0; mi < 2; mi++)
        #pragma unroll
        for (int ni = 0; ni < NI; ni++)
            #pragma unroll
            for (int j = 0; j < 4; j++) acc[mi][ni][j] = 0.f;

    const int aRow = tid >> 2;
    const int aCol = (tid & 3) << 2;
    const int bRow = tid / BTPR;
    const int bCol = (tid % BTPR) * 4;

    const float* Ab = A + (long)m0*K;
    const float* Bb = B + n0;
    const int nIter = K >> 4;

    #define ISSUE(it, stg) do {                                            \
        const float* Ag = Ab + ((it) << 4);                                \
        _Pragma("unroll")                                                  \
        for (int r = 0; r < 2; r++) {                                      \
            int row = aRow + r*64;                                         \
            uint32_t d_ = (uint32_t)__cvta_generic_to_shared(              \
                &As[stg][row*ASTRIDE + aCol]);                             \
            CP16(d_, Ag + (long)row*K + aCol);                             \
        }                                                                  \
        const float* Bg = Bb + (long)((it) << 4)*N;                        \
        _Pragma("unroll")                                                  \
        for (int r = 0; r < BPASS; r++) {                                  \
            int krow = bRow + r*BRPP;                                      \
            uint32_t d_ = (uint32_t)__cvta_generic_to_shared(              \
                &Bs[stg][krow*BSTRIDE + bCol]);                            \
            CP16(d_, Bg + (long)krow*N + bCol);                            \
        }                                                                  \
        asm volatile("cp.async.commit_group;");                            \
    } while (0)

    #define DO_KC(kc, stg) do {                                            \
        uint32_t af[2][4];                                                 \
        _Pragma("unroll")                                                  \
        for (int mi = 0; mi < 2; mi++) {                                   \
            int row = warpM*32 + mi*16 + gr;                               \
            af[mi][0] = __float_as_uint(As[stg][row*ASTRIDE + (kc) + gc]); \
            af[mi][1] = __float_as_uint(As[stg][(row+8)*ASTRIDE + (kc) + gc]); \
            af[mi][2] = __float_as_uint(As[stg][row*ASTRIDE + (kc) + gc + 4]); \
            af[mi][3] = __float_as_uint(As[stg][(row+8)*ASTRIDE + (kc) + gc + 4]); \
        }                                                                  \
        uint32_t bf[NI][2];                                                \
        _Pragma("unroll")                                                  \
        for (int ni = 0; ni < NI; ni++) {                                  \
            int col = warpN*(BN/2) + ni*8 + gr;                            \
            bf[ni][0] = __float_as_uint(Bs[stg][((kc)+gc)*BSTRIDE + col]); \
            bf[ni][1] = __float_as_uint(Bs[stg][((kc)+gc+4)*BSTRIDE + col]); \
        }                                                                  \
        _Pragma("unroll")                                                  \
        for (int mi = 0; mi < 2; mi++)                                     \
            _Pragma("unroll")                                              \
            for (int ni = 0; ni < NI; ni++)                                \
                MMA_TF32(acc[mi][ni], af[mi], bf[ni]);                     \
    } while (0)

    ISSUE(0, 0); ISSUE(1, 1); ISSUE(2, 2);

    for (int it = 0; it < nIter; it++) {
        const int stg = it & (STAGES-1);
        if (it + 2 < nIter)      asm volatile("cp.async.wait_group 2;");
        else if (it + 1 < nIter) asm volatile("cp.async.wait_group 1;");
        else                     asm volatile("cp.async.wait_group 0;");
        __syncthreads();

        DO_KC(kcFirst, stg);
        if (it + 3 < nIter) ISSUE(it + 3, (it + 3) & (STAGES-1));
        DO_KC(kcSecond, stg);
    }
    #undef DO_KC
    #undef ISSUE

    #pragma unroll
    for (int mi = 0; mi < 2; mi++) {
        #pragma unroll
        for (int rr = 0; rr < 2; rr++) {
            long row = m0 + warpM*32 + mi*16 + gr + rr*8;
            #pragma unroll
            for (int ni = 0; ni < NI; ni++) {
                int col = n0 + warpN*(BN/2) + ni*8 + gc*2;
                float v0 = acc[mi][ni][rr*2+0];
                float v1 = acc[mi][ni][rr*2+1];
                if (BIAS) { v0 += bias[col]; v1 += bias[col+1]; }
                if (RES)  {
                    float2 rv = *(const float2*)(res + row*N + col);
                    v0 += rv.x; v1 += rv.y;
                }
                if (RELU) { v0 = fmaxf(v0, 0.f); v1 = fmaxf(v1, 0.f); }
                if (ROUND){ v0 = tf32r(v0); v1 = tf32r(v1); }
                float2 ov; ov.x = v0; ov.y = v1;
                *(float2*)(C + row*N + col) = ov;
            }
        }
    }
}

// ---- flash attention: 4-way in-block split-K, f32x2 math (R12 core) -------
// 256 threads = 4 quarters x 64 q-threads. Quarter k processes tiles
// [k*nT/4, (k+1)*nT/4); each quarter has its own 8KB K/V smem region.
// Per-thread sequential tiles HALVED vs the 2-way version; merge = 2-stage
// in-smem tree (1,3 publish -> 0,2 merge; 2 publishes -> 0 merges+writes).
#define TQ 64
#define TS 16
__global__ void __launch_bounds__(256)
flash_attn_kernel(const float* __restrict__ qkv, float* __restrict__ out) {
    __shared__ float KV[4][2][TS*DH];   // [quarter][k/v][s*DH+d]  32KB
    __shared__ float mlA[2][2][TQ];     // stage-1 (m,l) from quarters 1,3
    __shared__ float mlB[2][TQ];        // stage-2 (m,l) from quarter 2
    const int q0 = (gridDim.x - 1 - blockIdx.x) * TQ;  // longest first
    const int bh = blockIdx.y;
    const int b  = bh / HH;
    const int h  = bh % HH;
    const int tid   = threadIdx.x;
    const int tq    = tid & 63;
    const int khalf = tid >> 6;         // quarter 0..3
    const int t = q0 + tq;
    const float* base = qkv + (long)b*TT*QKVN;

    const uint32_t ksm = (uint32_t)__cvta_generic_to_shared(&KV[khalf][0][0]);
    const uint32_t vsm = (uint32_t)__cvta_generic_to_shared(&KV[khalf][1][0]);

    // q packed into f32x2 pairs
    uint64_t q2[DH/2];
    {
        const float4* qr = (const float4*)(base + (long)t*QKVN + h*DH);
        #pragma unroll
        for (int j = 0; j < DH/4; j++) {
            float4 v = qr[j];
            PACK2(q2[2*j+0], v.x, v.y);
            PACK2(q2[2*j+1], v.z, v.w);
        }
    }
    uint64_t acc2[DH/2];
    #pragma unroll
    for (int j = 0; j < DH/2; j++) acc2[j] = 0ull;
    float m = -1e30f, l = 0.f;

    const int nT = (q0 + TQ) / TS;      // multiple of 4
    const int nQ = nT >> 2;
    const int tile0 = khalf * nQ;

    for (int jt = 0; jt < nQ; jt++) {
        const int s0 = (tile0 + jt) * TS;
        __syncthreads();
        #pragma unroll
        for (int i = 0; i < 4; i++) {
            int idx = tq + i*64;
            int s  = idx >> 4;
            int d4 = (idx & 15) << 2;
            const float* kp = base + (long)(s0+s)*QKVN + CC + h*DH + d4;
            *(float4*)&KV[khalf][0][s*DH + d4] = *(const float4*)kp;
            *(float4*)&KV[khalf][1][s*DH + d4] = *(const float4*)(kp + CC);
        }
        __syncthreads();

        float sc[TS];
        float tmax = -1e30f;
        #pragma unroll
        for (int s = 0; s < TS; s++) {
            uint32_t ka = ksm + s*DH*4;
            uint64_t d0 = 0ull, d1 = 0ull, d2 = 0ull, d3 = 0ull;
            #pragma unroll
            for (int j = 0; j < DH/2; j += 4) {
                uint64_t k0, k1, k2, k3;
                LDS2B64(k0, k1, ka + j*8);
                LDS2B64(k2, k3, ka + (j+2)*8);
                FMA2(d0, q2[j+0], k0);
                FMA2(d1, q2[j+1], k1);
                FMA2(d2, q2[j+2], k2);
                FMA2(d3, q2[j+3], k3);
            }
            ADD2(d0, d0, d1); ADD2(d2, d2, d3); ADD2(d0, d0, d2);
            float lo, hi; UNPACK2(lo, hi, d0);
            float d = lo + hi;
            sc[s] = (s0 + s <= t) ? d * 0.125f : -1e30f;
            tmax = fmaxf(tmax, sc[s]);
        }
        if (tmax > -1e29f) {
            float m_new = fmaxf(m, tmax);
            float alpha = __expf(m - m_new);
            l *= alpha;
            uint64_t a2; PACK2(a2, alpha, alpha);
            #pragma unroll
            for (int j = 0; j < DH/2; j++) MUL2(acc2[j], acc2[j], a2);
            #pragma unroll
            for (int s = 0; s < TS; s++) {
                float p = (sc[s] > -1e29f) ? __expf(sc[s] - m_new) : 0.f;
                l += p;
                uint64_t p2; PACK2(p2, p, p);
                uint32_t va = vsm + s*DH*4;
                #pragma unroll
                for (int j = 0; j < DH/2; j += 2) {
                    uint64_t v0, v1;
                    LDS2B64(v0, v1, va + j*8);
                    FMA2(acc2[j+0], p2, v0);
                    FMA2(acc2[j+1], p2, v1);
                }
            }
            m = m_new;
        }
    }

    float acc[DH];
    #pragma unroll
    for (int j = 0; j < DH/2; j++) {
        float lo, hi; UNPACK2(lo, hi, acc2[j]);
        acc[2*j] = lo; acc[2*j+1] = hi;
    }

    float* xch = (float*)KV;               // 8192-float alias
    // stage 1: quarters 1,3 publish; 0,2 merge
    __syncthreads();
    if (khalf & 1) {
        const int reg = khalf >> 1;        // 0 or 1
        mlA[reg][0][tq] = m; mlA[reg][1][tq] = l;
        #pragma unroll
        for (int j = 0; j < DH; j++)
            xch[reg*4096 + tq*DH + ((j + tq) & 63)] = acc[j];
    }
    __syncthreads();
    if (!(khalf & 1)) {
        const int reg = khalf >> 1;
        float m1 = mlA[reg][0][tq], l1 = mlA[reg][1][tq];
        float ms = fmaxf(m, m1);
        float a0 = __expf(m - ms);
        float a1 = __expf(m1 - ms);
        l = l*a0 + l1*a1;
        #pragma unroll
        for (int j = 0; j < DH; j++)
            acc[j] = acc[j]*a0 + xch[reg*4096 + tq*DH + ((j + tq) & 63)]*a1;
        m = ms;
    }
    // stage 2: quarter 2 publishes; quarter 0 merges + writes
    __syncthreads();
    if (khalf == 2) {
        mlB[0][tq] = m; mlB[1][tq] = l;
        #pragma unroll
        for (int j = 0; j < DH; j++)
            xch[tq*DH + ((j + tq) & 63)] = acc[j];
    }
    __syncthreads();
    if (khalf == 0) {
        float m1 = mlB[0][tq], l1 = mlB[1][tq];
        float ms = fmaxf(m, m1);
        float a0 = __expf(m - ms);
        float a1 = __expf(m1 - ms);
        float inv = 1.0f / (l*a0 + l1*a1);
        float* o = out + ((long)b*TT + t)*CC + h*DH;
        #pragma unroll
        for (int j = 0; j < DH; j += 4) {
            float4 v;
            v.x = tf32r((acc[j+0]*a0 + xch[tq*DH + ((j+0+tq)&63)]*a1) * inv);
            v.y = tf32r((acc[j+1]*a0 + xch[tq*DH + ((j+1+tq)&63)]*a1) * inv);
            v.z = tf32r((acc[j+2]*a0 + xch[tq*DH + ((j+2+tq)&63)]*a1) * inv);
            v.w = tf32r((acc[j+3]*a0 + xch[tq*DH + ((j+3+tq)&63)]*a1) * inv);
            *(float4*)(o + j) = v;
        }
    }
}

// ---------------- cross-entropy: single-pass online softmax (float4) -------
__global__ void loss_rows_kernel(const float* __restrict__ logits,
                                 const int* __restrict__ targets) {
    __shared__ float sm[256], ss[256];
    const int row = blockIdx.x;
    const float4* lr4 = (const float4*)(logits + (long)row*VV);
    float m = -1e30f, s = 0.f;
    for (int c4 = threadIdx.x; c4 < VV/4; c4 += 256) {
        float4 v4 = lr4[c4];
        float vm = fmaxf(fmaxf(v4.x, v4.y), fmaxf(v4.z, v4.w));
        if (vm <= m) {
            s += __expf(v4.x - m) + __expf(v4.y - m)
               + __expf(v4.z - m) + __expf(v4.w - m);
        } else {
            s = s*__expf(m - vm)
              + __expf(v4.x - vm) + __expf(v4.y - vm)
              + __expf(v4.z - vm) + __expf(v4.w - vm);
            m = vm;
        }
    }
    sm[threadIdx.x] = m; ss[threadIdx.x] = s;
    __syncthreads();
    for (int o = 128; o > 0; o >>= 1) {
        if (threadIdx.x < o) {
            float m2 = sm[threadIdx.x+o], s2 = ss[threadIdx.x+o];
            float mm = fmaxf(sm[threadIdx.x], m2);
            ss[threadIdx.x] = ss[threadIdx.x]*__expf(sm[threadIdx.x]-mm)
                            + s2*__expf(m2-mm);
            sm[threadIdx.x] = mm;
        }
        __syncthreads();
    }
    if (threadIdx.x == 0) {
        float lse = sm[0] + logf(ss[0]);
        g_rowloss[row] = lse - logits[(long)row*VV + targets[row]];
    }
}

__global__ void loss_reduce_kernel(float* __restrict__ out) {
    __shared__ float red[256];
    float s = 0.f;
    for (int i = threadIdx.x; i < BT; i += 256) s += g_rowloss[i];
    red[threadIdx.x] = s; __syncthreads();
    for (int o = 128; o > 0; o >>= 1) {
        if (threadIdx.x < o) red[threadIdx.x] += red[threadIdx.x+o];
        __syncthreads();
    }
    if (threadIdx.x == 0) *out = red[0] * (1.0f/BT);
}

// ---------------- driver ----------------------------------------------------
extern "C" void kernel_launch(void* const* d_in, const int* in_sizes, int n_in,
                              void* d_out, int out_size) {
    const int*   idx     = (const int*)  d_in[0];
    const int*   targets = (const int*)  d_in[1];
    const float* tok_emb = (const float*)d_in[2];
    const float* pos_emb = (const float*)d_in[3];
    const float* Wq      = (const float*)d_in[4];
    const float* Wk      = (const float*)d_in[5];
    const float* Wv      = (const float*)d_in[6];
    const float* Wproj   = (const float*)d_in[7];
    const float* bproj   = (const float*)d_in[8];
    const float* ln1_g   = (const float*)d_in[9];
    const float* ln1_b   = (const float*)d_in[10];
    const float* ln2_g   = (const float*)d_in[11];
    const float* ln2_b   = (const float*)d_in[12];
    const float* W1      = (const float*)d_in[13];
    const float* b1      = (const float*)d_in[14];
    const float* W2      = (const float*)d_in[15];
    const float* b2      = (const float*)d_in[16];
    const float* Wlm     = (const float*)d_in[17];
    const float* blm     = (const float*)d_in[18];
    float* out = (float*)d_out;

    float* xp;    cudaGetSymbolAddress((void**)&xp,    g_x);
    float* hp;    cudaGetSymbolAddress((void**)&hp,    g_h);
    float* qkvp;  cudaGetSymbolAddress((void**)&qkvp,  g_qkv);
    float* attnp; cudaGetSymbolAddress((void**)&attnp, g_attn);
    float* hidp;  cudaGetSymbolAddress((void**)&hidp,  g_hid);
    float* wqkvp; cudaGetSymbolAddress((void**)&wqkvp, g_wqkv);
    float* wprojp;cudaGetSymbolAddress((void**)&wprojp,g_wproj);
    float* w1p;   cudaGetSymbolAddress((void**)&w1p,   g_w1);
    float* w2p;   cudaGetSymbolAddress((void**)&w2p,   g_w2);
    float* wlmp;  cudaGetSymbolAddress((void**)&wlmp,  g_wlm);

    // Launch order: 0:pack 1:embed_ln 2:QKV 3:ATTENTION (ncu capture slot)
    pack_qkv_kernel<<<2048, 256>>>(Wq, Wk, Wv);
    embed_ln_kernel<<<BT, 256>>>(idx, tok_emb, pos_emb, ln1_g, ln1_b);

    for (int l = 0; l < LL; l++) {
        if (l > 0)
            layernorm_kernel<<<BT, 256>>>(xp, ln1_g + l*CC, ln1_b + l*CC, hp);

        // qkv = h @ Wqkv[l]    [2048,768]x[768,2304]
        gemm_tf32_kernel<128,false,false,false,false>
            <<<dim3(BT/128, QKVN/128), 256>>>(
            hp, wqkvp + (long)l*CC*QKVN, nullptr, nullptr, qkvp, BT, QKVN, CC);

        flash_attn_kernel<<<dim3(TT/TQ, BB*HH), 256>>>(qkvp, attnp);

        if (l == 0) {
            round_copy2_kernel<<<2048, 256>>>(Wproj, wprojp, (long)LL*CC*CC,
                                              W1,    w1p,    (long)LL*CC*HID);
            round_copy2_kernel<<<4096, 256>>>(W2,    w2p,    (long)LL*HID*CC,
                                              Wlm,   wlmp,   (long)CC*VV);
        }

        // x = x + attn @ Wproj[l] + bproj[l]   (BN=64: grid 16x12)
        gemm_tf32_kernel<64,true,false,true,false>
            <<<dim3(BT/128, CC/64), 256>>>(
            attnp, wprojp + (long)l*CC*CC, bproj + l*CC, xp, xp, BT, CC, CC);

        layernorm_kernel<<<BT, 256>>>(xp, ln2_g + l*CC, ln2_b + l*CC, hp);

        // hid = relu(h @ W1[l] + b1[l])  (rounded output: feeds next GEMM)
        gemm_tf32_kernel<128,true,true,false,true>
            <<<dim3(BT/128, HID/128), 256>>>(
            hp, w1p + (long)l*CC*HID, b1 + (long)l*HID, nullptr, hidp, BT, HID, CC);

        // x = x + hid @ W2[l] + b2[l]  (BN=64); last layer fuses tf32-round
        if (l == LL-1) {
            gemm_tf32_kernel<64,true,false,true,true>
                <<<dim3(BT/128, CC/64), 256>>>(
                hidp, w2p + (long)l*HID*CC, b2 + l*CC, xp, hp, BT, CC, HID);
        } else {
            gemm_tf32_kernel<64,true,false,true,false>
                <<<dim3(BT/128, CC/64), 256>>>(
                hidp, w2p + (long)l*HID*CC, b2 + l*CC, xp, xp, BT, CC, HID);
        }
    }

    // logits = x @ Wlm + blm -> d_out
    gemm_tf32_kernel<128,true,false,false,false>
        <<<dim3(BT/128, VV/128), 256>>>(
        hp, wlmp, blm, nullptr, out, BT, VV, CC);

    loss_rows_kernel<<<BT, 256>>>(out, targets);
    if (out_size >= BT*VV + 1) {
        loss_reduce_kernel<<<1, 256>>>(out + (long)BT*VV);
    } else if (out_size == 1) {
        loss_reduce_kernel<<<1, 256>>>(out);
    }
}